// round 5
// baseline (speedup 1.0000x reference)
#include <cuda_runtime.h>

// ---------------- problem constants ----------------
#define NTHREADS 448         // 14 warps: 2 row-groups x 224
#define NB       14          // batch rows per CTA
#define NBT      7           // batch rows per thread (row-split)
#define NCTA     148
#define BB       2048
#define TSTEPS   512
#define PP       17
#define HH       50
#define GG       200         // 4*H gates
#define TT       544         // T + future/P
#define XW       (TSTEPS*PP)
#define OUTW     (TT*PP)
#define KP       52          // padded hidden stride
#define XP       20          // padded input stride
#define NCH      13          // KP/4 chunks per 52-float vector

// ---------------- smem layout (float offsets) ----------------
// W2/W3 repacked conflict-free: [26 chunks][200 gates][4 k] ; chunks 0..12 = Wih, 13..25 = Whh
#define OFF_W2   0           // 26*200*4 = 20800
#define OFF_W3   20800
#define OFF_B2   41600       // 200
#define OFF_B3   41800       // 200
#define OFF_WLIN 42000       // 17*52 = 884
#define OFF_BLIN 42884       // 17 (+3 pad)
#define OFF_GS   42904       // 14*200 = 2800
#define OFF_HS1  45704       // 14*52
#define OFF_HS2  46432
#define OFF_HS3  47160
#define OFF_XS   47888       // 14*20
#define SMEM_FLOATS 48168    // ~192.7 KB

__device__ __forceinline__ float fsig(float x) {
    return __fdividef(1.0f, 1.0f + __expf(-x));
}
__device__ __forceinline__ float ftanh_(float x) {
    return 2.0f * __fdividef(1.0f, 1.0f + __expf(-2.0f * x)) - 1.0f;
}

extern __shared__ float sm[];

// layers 2/3 gates: conflict-free repacked weights, row-split batch.
__device__ __forceinline__ void gates23(
    const float* __restrict__ W, const float* __restrict__ Hin,
    const float* __restrict__ Hsame, const float* __restrict__ Bsm,
    float* __restrict__ GS, int g, bool gok, int rbase)
{
    float acc[NBT];
    const float bg = Bsm[g];
#pragma unroll
    for (int r = 0; r < NBT; r++) acc[r] = bg;

#pragma unroll
    for (int c = 0; c < NCH; c++) {
        float4 wx = *(const float4*)(W + (size_t)(c * GG + g) * 4);
        float4 wh = *(const float4*)(W + (size_t)((NCH + c) * GG + g) * 4);
#pragma unroll
        for (int r = 0; r < NBT; r++) {
            float4 a = *(const float4*)(Hin   + (rbase + r) * KP + c * 4);
            float4 b = *(const float4*)(Hsame + (rbase + r) * KP + c * 4);
            acc[r] = fmaf(wx.x, a.x, acc[r]);
            acc[r] = fmaf(wx.y, a.y, acc[r]);
            acc[r] = fmaf(wx.z, a.z, acc[r]);
            acc[r] = fmaf(wx.w, a.w, acc[r]);
            acc[r] = fmaf(wh.x, b.x, acc[r]);
            acc[r] = fmaf(wh.y, b.y, acc[r]);
            acc[r] = fmaf(wh.z, b.z, acc[r]);
            acc[r] = fmaf(wh.w, b.w, acc[r]);
        }
    }
    if (gok) {
#pragma unroll
        for (int r = 0; r < NBT; r++) GS[(rbase + r) * GG + g] = acc[r];
    }
}

// LSTM pointwise: 2 work items per thread cover NB*H = 700 outputs (448*2 = 896).
__device__ __forceinline__ void act_layer(
    const float* __restrict__ GS, float* __restrict__ Hdst,
    float (&c)[2], const int (&ar)[2], const int (&aj)[2], const bool (&av)[2])
{
#pragma unroll
    for (int q = 0; q < 2; q++) {
        if (av[q]) {
            int base = ar[q] * GG + aj[q];
            float xi = GS[base];
            float xf = GS[base + HH];
            float xg = GS[base + 2 * HH];
            float xo = GS[base + 3 * HH];
            float iv = fsig(xi), fv = fsig(xf), gv = ftanh_(xg), ov = fsig(xo);
            float cn = fmaf(fv, c[q], iv * gv);
            c[q] = cn;
            Hdst[ar[q] * KP + aj[q]] = ov * ftanh_(cn);
        }
    }
}

__global__ void __launch_bounds__(NTHREADS, 1)
lstm_forward(const float* __restrict__ x,
             const float* __restrict__ Wih1, const float* __restrict__ Whh1,
             const float* __restrict__ bih1, const float* __restrict__ bhh1,
             const float* __restrict__ Wih2, const float* __restrict__ Whh2,
             const float* __restrict__ bih2, const float* __restrict__ bhh2,
             const float* __restrict__ Wih3, const float* __restrict__ Whh3,
             const float* __restrict__ bih3, const float* __restrict__ bhh3,
             const float* __restrict__ Wlin, const float* __restrict__ blin,
             float* __restrict__ out)
{
    const int tid  = threadIdx.x;
    const int row0 = blockIdx.x * NB;

    // gate-thread mapping: two row-halves of 224 threads, 200 gate rows each
    const int  lt    = tid % 224;
    const bool gok   = (lt < GG);
    const int  g     = gok ? lt : 0;
    const int  rbase = (tid / 224) * NBT;   // 0 or 7

    // ---- cooperative weight load: repack W2/W3 conflict-free ----
    // layout [c][g][j], c<13: Wih k=c*4+j ; c>=13: Whh k=(c-13)*4+j (zero pad k>=50)
    for (int idx = tid; idx < 26 * GG * 4; idx += NTHREADS) {
        int c   = idx / (GG * 4);
        int rem = idx - c * (GG * 4);
        int gg  = rem >> 2;
        int j   = rem & 3;
        float v2, v3;
        if (c < NCH) {
            int k = c * 4 + j;
            v2 = (k < HH) ? Wih2[gg * HH + k] : 0.f;
            v3 = (k < HH) ? Wih3[gg * HH + k] : 0.f;
        } else {
            int k = (c - NCH) * 4 + j;
            v2 = (k < HH) ? Whh2[gg * HH + k] : 0.f;
            v3 = (k < HH) ? Whh3[gg * HH + k] : 0.f;
        }
        sm[OFF_W2 + idx] = v2;
        sm[OFF_W3 + idx] = v3;
    }
    for (int idx = tid; idx < GG; idx += NTHREADS) {
        sm[OFF_B2 + idx] = bih2[idx] + bhh2[idx];
        sm[OFF_B3 + idx] = bih3[idx] + bhh3[idx];
    }
    for (int idx = tid; idx < PP * KP; idx += NTHREADS) {
        int p = idx / KP, k = idx - p * KP;
        sm[OFF_WLIN + idx] = (k < HH) ? Wlin[p * HH + k] : 0.f;
    }
    if (tid < PP) sm[OFF_BLIN + tid] = blin[tid];
    for (int idx = tid; idx < 3 * NB * KP; idx += NTHREADS) sm[OFF_HS1 + idx] = 0.f;
    for (int idx = tid; idx < NB * XP; idx += NTHREADS)     sm[OFF_XS  + idx] = 0.f;

    // ---- layer-1 weights in registers ----
    float w1x[XP], w1h[KP], bg1;
    {
#pragma unroll
        for (int k = 0; k < XP; k++) w1x[k] = (k < PP) ? Wih1[g * PP + k] : 0.f;
#pragma unroll
        for (int k = 0; k < KP; k++) w1h[k] = (k < HH) ? Whh1[g * HH + k] : 0.f;
        bg1 = bih1[g] + bhh1[g];
    }

    // ---- per-thread work-item maps ----
    int ar[2], aj[2]; bool av[2];              // activation items (NB*H = 700)
#pragma unroll
    for (int q = 0; q < 2; q++) {
        int it = tid + q * NTHREADS;
        av[q] = (it < NB * HH);
        int r = it / HH;
        ar[q] = r; aj[q] = it - r * HH;
    }
    const bool hv = (tid < NB * PP);           // head / x-load item (238)
    const int  hr = hv ? tid / PP : 0;
    const int  hp = hv ? tid - hr * PP : 0;

    float c1[2] = {0.f, 0.f};
    float c2[2] = {0.f, 0.f};
    float c3[2] = {0.f, 0.f};

    // ---- prefetch x for t=0 ----
    float xreg = 0.f;
    if (hv) {
        int brow = row0 + hr;
        if (brow < BB) xreg = x[(size_t)brow * XW + hp];
    }
    __syncthreads();

    // ================= time loop =================
    for (int t = 0; t < TT; t++) {
        if (t < TSTEPS) {
            if (hv) sm[OFF_XS + hr * XP + hp] = xreg;
        }
        __syncthreads();                                   // S0: XS ready

        // prefetch next step's x
        if (t + 1 < TSTEPS && hv) {
            int brow = row0 + hr;
            xreg = (brow < BB) ? x[(size_t)brow * XW + (t + 1) * PP + hp] : 0.f;
        }

        // ---- layer 1 gates: register weights ----
        {
            float acc[NBT];
#pragma unroll
            for (int r = 0; r < NBT; r++) acc[r] = bg1;
#pragma unroll
            for (int c = 0; c < XP / 4; c++) {
#pragma unroll
                for (int r = 0; r < NBT; r++) {
                    float4 v = *(const float4*)(sm + OFF_XS + (rbase + r) * XP + c * 4);
                    acc[r] = fmaf(w1x[c * 4    ], v.x, acc[r]);
                    acc[r] = fmaf(w1x[c * 4 + 1], v.y, acc[r]);
                    acc[r] = fmaf(w1x[c * 4 + 2], v.z, acc[r]);
                    acc[r] = fmaf(w1x[c * 4 + 3], v.w, acc[r]);
                }
            }
#pragma unroll
            for (int c = 0; c < NCH; c++) {
#pragma unroll
                for (int r = 0; r < NBT; r++) {
                    float4 v = *(const float4*)(sm + OFF_HS1 + (rbase + r) * KP + c * 4);
                    acc[r] = fmaf(w1h[c * 4    ], v.x, acc[r]);
                    acc[r] = fmaf(w1h[c * 4 + 1], v.y, acc[r]);
                    acc[r] = fmaf(w1h[c * 4 + 2], v.z, acc[r]);
                    acc[r] = fmaf(w1h[c * 4 + 3], v.w, acc[r]);
                }
            }
            if (gok) {
#pragma unroll
                for (int r = 0; r < NBT; r++) sm[OFF_GS + (rbase + r) * GG + g] = acc[r];
            }
        }
        __syncthreads();                                   // S1
        act_layer(sm + OFF_GS, sm + OFF_HS1, c1, ar, aj, av);
        __syncthreads();                                   // S2

        gates23(sm + OFF_W2, sm + OFF_HS1, sm + OFF_HS2, sm + OFF_B2,
                sm + OFF_GS, g, gok, rbase);
        __syncthreads();                                   // S3
        act_layer(sm + OFF_GS, sm + OFF_HS2, c2, ar, aj, av);
        __syncthreads();                                   // S4

        gates23(sm + OFF_W3, sm + OFF_HS2, sm + OFF_HS3, sm + OFF_B3,
                sm + OFF_GS, g, gok, rbase);
        __syncthreads();                                   // S5
        act_layer(sm + OFF_GS, sm + OFF_HS3, c3, ar, aj, av);
        __syncthreads();                                   // S6

        // ---- linear head + output store (+ autoregressive feedback) ----
        if (hv) {
            float acc = sm[OFF_BLIN + hp];
#pragma unroll
            for (int kk = 0; kk < KP; kk += 4) {
                float4 w = *(const float4*)(sm + OFF_WLIN + hp * KP + kk);
                float4 h = *(const float4*)(sm + OFF_HS3  + hr * KP + kk);
                acc = fmaf(w.x, h.x, acc);
                acc = fmaf(w.y, h.y, acc);
                acc = fmaf(w.z, h.z, acc);
                acc = fmaf(w.w, h.w, acc);
            }
            int brow = row0 + hr;
            if (brow < BB) out[(size_t)brow * OUTW + t * PP + hp] = acc;
            if (t >= TSTEPS - 1) sm[OFF_XS + hr * XP + hp] = acc;
        }
        // loop-top S0 orders XS feedback vs. next layer-1 reads
    }
}

extern "C" void kernel_launch(void* const* d_in, const int* in_sizes, int n_in,
                              void* d_out, int out_size)
{
    const float* x    = (const float*)d_in[0];
    const float* Wih1 = (const float*)d_in[1];
    const float* Whh1 = (const float*)d_in[2];
    const float* bih1 = (const float*)d_in[3];
    const float* bhh1 = (const float*)d_in[4];
    const float* Wih2 = (const float*)d_in[5];
    const float* Whh2 = (const float*)d_in[6];
    const float* bih2 = (const float*)d_in[7];
    const float* bhh2 = (const float*)d_in[8];
    const float* Wih3 = (const float*)d_in[9];
    const float* Whh3 = (const float*)d_in[10];
    const float* bih3 = (const float*)d_in[11];
    const float* bhh3 = (const float*)d_in[12];
    const float* Wlin = (const float*)d_in[13];
    const float* blin = (const float*)d_in[14];
    float* out = (float*)d_out;

    const size_t smem = (size_t)SMEM_FLOATS * sizeof(float);
    cudaFuncSetAttribute(lstm_forward,
                         cudaFuncAttributeMaxDynamicSharedMemorySize, (int)smem);
    lstm_forward<<<NCTA, NTHREADS, smem>>>(
        x, Wih1, Whh1, bih1, bhh1, Wih2, Whh2, bih2, bhh2,
        Wih3, Whh3, bih3, bhh3, Wlin, blin, out);
}

// round 7
// speedup vs baseline: 1.3236x; 1.3236x over previous
#include <cuda_runtime.h>
#include <cstdint>

// ---------------- problem constants ----------------
#define NTHREADS 224
#define NB       14          // batch rows per CTA (2048/148 -> 14)
#define NCTA     148
#define BB       2048
#define TSTEPS   512
#define PP       17
#define HH       50
#define GG       200         // 4*H gates
#define TT       544         // T + future/P
#define XW       (TSTEPS*PP)
#define OUTW     (TT*PP)
#define KP       52          // padded hidden stride
#define XP       20          // padded input stride
#define NCH      13          // KP/4 chunks

// ---------------- smem layout (float offsets) ----------------
// W2/W3 conflict-free: [26 chunks][200 gates][4 k]; chunks 0..12 = Wih, 13..25 = Whh
#define OFF_W2   0           // 20800
#define OFF_W3   20800
#define OFF_B2   41600       // 200
#define OFF_B3   41800       // 200
#define OFF_WLIN 42000       // 17*52 = 884
#define OFF_BLIN 42884       // 17 (+3 pad)
#define OFF_GS   42904       // 14*200
#define OFF_HS1  45704       // 14*52
#define OFF_HS2  46432
#define OFF_HS3  47160
#define OFF_XS   47888       // 14*20
#define SMEM_FLOATS 48168    // ~192.7 KB

// ---------------- packed f32x2 helpers ----------------
__device__ __forceinline__ void ffma2(uint64_t& d, uint64_t a, uint64_t b) {
    asm("fma.rn.f32x2 %0, %1, %2, %0;" : "+l"(d) : "l"(a), "l"(b));
}
__device__ __forceinline__ uint64_t pack2(float lo, float hi) {
    uint64_t r;
    asm("mov.b64 %0, {%1, %2};" : "=l"(r) : "f"(lo), "f"(hi));
    return r;
}
__device__ __forceinline__ float hadd2(uint64_t v) {
    float lo, hi;
    asm("mov.b64 {%0, %1}, %2;" : "=f"(lo), "=f"(hi) : "l"(v));
    return lo + hi;
}

__device__ __forceinline__ float fsig(float x) {
    return __fdividef(1.0f, 1.0f + __expf(-x));
}
__device__ __forceinline__ float ftanh_(float x) {
    return 2.0f * __fdividef(1.0f, 1.0f + __expf(-2.0f * x)) - 1.0f;
}

extern __shared__ float sm[];

// layers 2/3 gates: conflict-free smem weights, packed-k FMA.
__device__ __forceinline__ void gates23(
    const float* __restrict__ W, const float* __restrict__ Hin,
    const float* __restrict__ Hsame, const float* __restrict__ Bsm,
    float* __restrict__ GS, int g, bool gok)
{
    uint64_t acc[NB];
    const float bg = Bsm[g];
#pragma unroll
    for (int r = 0; r < NB; r++) acc[r] = pack2(bg, 0.f);

#pragma unroll
    for (int c = 0; c < NCH; c++) {
        ulonglong2 wx = *(const ulonglong2*)(W + (size_t)(c * GG + g) * 4);
        ulonglong2 wh = *(const ulonglong2*)(W + (size_t)((NCH + c) * GG + g) * 4);
#pragma unroll
        for (int r = 0; r < NB; r++) {
            ulonglong2 a = *(const ulonglong2*)(Hin   + r * KP + c * 4);
            ulonglong2 b = *(const ulonglong2*)(Hsame + r * KP + c * 4);
            ffma2(acc[r], wx.x, a.x);
            ffma2(acc[r], wx.y, a.y);
            ffma2(acc[r], wh.x, b.x);
            ffma2(acc[r], wh.y, b.y);
        }
    }
    if (gok) {
#pragma unroll
        for (int r = 0; r < NB; r++) GS[r * GG + g] = hadd2(acc[r]);
    }
}

// LSTM pointwise: 4 items/thread cover NB*H = 700 outputs.
__device__ __forceinline__ void act_layer(
    const float* __restrict__ GS, float* __restrict__ Hdst,
    float (&c)[4], const int (&ar)[4], const int (&aj)[4], const bool (&av)[4])
{
#pragma unroll
    for (int q = 0; q < 4; q++) {
        if (av[q]) {
            int base = ar[q] * GG + aj[q];
            float xi = GS[base];
            float xf = GS[base + HH];
            float xg = GS[base + 2 * HH];
            float xo = GS[base + 3 * HH];
            float iv = fsig(xi), fv = fsig(xf), gv = ftanh_(xg), ov = fsig(xo);
            float cn = fmaf(fv, c[q], iv * gv);
            c[q] = cn;
            Hdst[ar[q] * KP + aj[q]] = ov * ftanh_(cn);
        }
    }
}

__global__ void __launch_bounds__(NTHREADS, 1)
lstm_forward(const float* __restrict__ x,
             const float* __restrict__ Wih1, const float* __restrict__ Whh1,
             const float* __restrict__ bih1, const float* __restrict__ bhh1,
             const float* __restrict__ Wih2, const float* __restrict__ Whh2,
             const float* __restrict__ bih2, const float* __restrict__ bhh2,
             const float* __restrict__ Wih3, const float* __restrict__ Whh3,
             const float* __restrict__ bih3, const float* __restrict__ bhh3,
             const float* __restrict__ Wlin, const float* __restrict__ blin,
             float* __restrict__ out)
{
    const int tid  = threadIdx.x;
    const int row0 = blockIdx.x * NB;

    const bool gok = (tid < GG);
    const int  g   = gok ? tid : 0;

    // ---- cooperative weight load: repack W2/W3 conflict-free [c][g][4] ----
    for (int idx = tid; idx < 26 * GG * 4; idx += NTHREADS) {
        int c   = idx / (GG * 4);
        int rem = idx - c * (GG * 4);
        int gg  = rem >> 2;
        int j   = rem & 3;
        float v2, v3;
        if (c < NCH) {
            int k = c * 4 + j;
            v2 = (k < HH) ? Wih2[gg * HH + k] : 0.f;
            v3 = (k < HH) ? Wih3[gg * HH + k] : 0.f;
        } else {
            int k = (c - NCH) * 4 + j;
            v2 = (k < HH) ? Whh2[gg * HH + k] : 0.f;
            v3 = (k < HH) ? Whh3[gg * HH + k] : 0.f;
        }
        sm[OFF_W2 + idx] = v2;
        sm[OFF_W3 + idx] = v3;
    }
    for (int idx = tid; idx < GG; idx += NTHREADS) {
        sm[OFF_B2 + idx] = bih2[idx] + bhh2[idx];
        sm[OFF_B3 + idx] = bih3[idx] + bhh3[idx];
    }
    for (int idx = tid; idx < PP * KP; idx += NTHREADS) {
        int p = idx / KP, k = idx - p * KP;
        sm[OFF_WLIN + idx] = (k < HH) ? Wlin[p * HH + k] : 0.f;
    }
    if (tid < PP) sm[OFF_BLIN + tid] = blin[tid];
    for (int idx = tid; idx < 3 * NB * KP; idx += NTHREADS) sm[OFF_HS1 + idx] = 0.f;
    for (int idx = tid; idx < NB * XP; idx += NTHREADS)     sm[OFF_XS  + idx] = 0.f;

    // ---- layer-1 weights in registers as packed k-pairs ----
    uint64_t w1x2[XP / 2];   // 10 pairs (17 real)
    uint64_t w1h2[KP / 2];   // 26 pairs (50 real)
    float bg1;
    {
#pragma unroll
        for (int i = 0; i < XP / 2; i++) {
            int k0 = 2 * i, k1 = 2 * i + 1;
            float a = (k0 < PP) ? Wih1[g * PP + k0] : 0.f;
            float b = (k1 < PP) ? Wih1[g * PP + k1] : 0.f;
            w1x2[i] = pack2(a, b);
        }
#pragma unroll
        for (int i = 0; i < KP / 2; i++) {
            int k0 = 2 * i, k1 = 2 * i + 1;
            float a = (k0 < HH) ? Whh1[g * HH + k0] : 0.f;
            float b = (k1 < HH) ? Whh1[g * HH + k1] : 0.f;
            w1h2[i] = pack2(a, b);
        }
        bg1 = bih1[g] + bhh1[g];
    }

    // ---- per-thread work-item maps ----
    int ar[4], aj[4]; bool av[4];              // activation items (700)
#pragma unroll
    for (int q = 0; q < 4; q++) {
        int it = tid + q * NTHREADS;
        av[q] = (it < NB * HH);
        int r = it / HH;
        ar[q] = r; aj[q] = it - r * HH;
    }
    int orr[2], op[2]; bool ov[2];             // head / x-load items (238)
#pragma unroll
    for (int q = 0; q < 2; q++) {
        int it = tid + q * NTHREADS;
        ov[q] = (it < NB * PP);
        int r = it / PP;
        orr[q] = r; op[q] = it - r * PP;
    }
    float c1[4] = {0.f,0.f,0.f,0.f};
    float c2[4] = {0.f,0.f,0.f,0.f};
    float c3[4] = {0.f,0.f,0.f,0.f};

    // ---- prefetch x for t=0 ----
    float xreg[2] = {0.f, 0.f};
#pragma unroll
    for (int q = 0; q < 2; q++) {
        if (ov[q]) {
            int brow = row0 + orr[q];
            if (brow < BB) xreg[q] = x[(size_t)brow * XW + op[q]];
        }
    }
    __syncthreads();

    // ================= time loop =================
    for (int t = 0; t < TT; t++) {
        if (t < TSTEPS) {
#pragma unroll
            for (int q = 0; q < 2; q++)
                if (ov[q]) sm[OFF_XS + orr[q] * XP + op[q]] = xreg[q];
        }
        __syncthreads();                                   // S0: XS ready

        // prefetch next step's x
        if (t + 1 < TSTEPS) {
#pragma unroll
            for (int q = 0; q < 2; q++) {
                if (ov[q]) {
                    int brow = row0 + orr[q];
                    xreg[q] = (brow < BB)
                        ? x[(size_t)brow * XW + (t + 1) * PP + op[q]] : 0.f;
                }
            }
        }

        // ---- layer 1 gates: register weights, packed-k FMA ----
        {
            uint64_t acc[NB];
#pragma unroll
            for (int r = 0; r < NB; r++) acc[r] = pack2(bg1, 0.f);
#pragma unroll
            for (int c = 0; c < XP / 4; c++) {
#pragma unroll
                for (int r = 0; r < NB; r++) {
                    ulonglong2 v = *(const ulonglong2*)(sm + OFF_XS + r * XP + c * 4);
                    ffma2(acc[r], w1x2[2 * c    ], v.x);
                    ffma2(acc[r], w1x2[2 * c + 1], v.y);
                }
            }
#pragma unroll
            for (int c = 0; c < NCH; c++) {
#pragma unroll
                for (int r = 0; r < NB; r++) {
                    ulonglong2 v = *(const ulonglong2*)(sm + OFF_HS1 + r * KP + c * 4);
                    ffma2(acc[r], w1h2[2 * c    ], v.x);
                    ffma2(acc[r], w1h2[2 * c + 1], v.y);
                }
            }
            if (gok) {
#pragma unroll
                for (int r = 0; r < NB; r++) sm[OFF_GS + r * GG + g] = hadd2(acc[r]);
            }
        }
        __syncthreads();                                   // S1
        act_layer(sm + OFF_GS, sm + OFF_HS1, c1, ar, aj, av);
        __syncthreads();                                   // S2

        gates23(sm + OFF_W2, sm + OFF_HS1, sm + OFF_HS2, sm + OFF_B2,
                sm + OFF_GS, g, gok);
        __syncthreads();                                   // S3
        act_layer(sm + OFF_GS, sm + OFF_HS2, c2, ar, aj, av);
        __syncthreads();                                   // S4

        gates23(sm + OFF_W3, sm + OFF_HS2, sm + OFF_HS3, sm + OFF_B3,
                sm + OFF_GS, g, gok);
        __syncthreads();                                   // S5
        act_layer(sm + OFF_GS, sm + OFF_HS3, c3, ar, aj, av);
        __syncthreads();                                   // S6

        // ---- linear head (packed) + output store (+ autoregressive feedback) ----
#pragma unroll
        for (int q = 0; q < 2; q++) {
            if (ov[q]) {
                int r = orr[q], p = op[q];
                uint64_t acc = pack2(sm[OFF_BLIN + p], 0.f);
#pragma unroll
                for (int c = 0; c < NCH; c++) {
                    ulonglong2 w = *(const ulonglong2*)(sm + OFF_WLIN + p * KP + c * 4);
                    ulonglong2 h = *(const ulonglong2*)(sm + OFF_HS3  + r * KP + c * 4);
                    ffma2(acc, w.x, h.x);
                    ffma2(acc, w.y, h.y);
                }
                float res = hadd2(acc);
                int brow = row0 + r;
                if (brow < BB) out[(size_t)brow * OUTW + t * PP + p] = res;
                if (t >= TSTEPS - 1) sm[OFF_XS + r * XP + p] = res;
            }
        }
        // loop-top S0 orders XS feedback vs. next layer-1 reads
    }
}

extern "C" void kernel_launch(void* const* d_in, const int* in_sizes, int n_in,
                              void* d_out, int out_size)
{
    const float* x    = (const float*)d_in[0];
    const float* Wih1 = (const float*)d_in[1];
    const float* Whh1 = (const float*)d_in[2];
    const float* bih1 = (const float*)d_in[3];
    const float* bhh1 = (const float*)d_in[4];
    const float* Wih2 = (const float*)d_in[5];
    const float* Whh2 = (const float*)d_in[6];
    const float* bih2 = (const float*)d_in[7];
    const float* bhh2 = (const float*)d_in[8];
    const float* Wih3 = (const float*)d_in[9];
    const float* Whh3 = (const float*)d_in[10];
    const float* bih3 = (const float*)d_in[11];
    const float* bhh3 = (const float*)d_in[12];
    const float* Wlin = (const float*)d_in[13];
    const float* blin = (const float*)d_in[14];
    float* out = (float*)d_out;

    const size_t smem = (size_t)SMEM_FLOATS * sizeof(float);
    cudaFuncSetAttribute(lstm_forward,
                         cudaFuncAttributeMaxDynamicSharedMemorySize, (int)smem);
    lstm_forward<<<NCTA, NTHREADS, smem>>>(
        x, Wih1, Whh1, bih1, bhh1, Wih2, Whh2, bih2, bhh2,
        Wih3, Whh3, bih3, bhh3, Wlin, blin, out);
}

// round 10
// speedup vs baseline: 1.3397x; 1.0122x over previous
#include <cuda_runtime.h>
#include <cstdint>

// ---------------- problem constants ----------------
#define NTHREADS 448         // 14 warps: 2 row-groups x 7 warps
#define NB       14          // batch rows per CTA
#define NBT      7           // batch rows per thread (row split)
#define NCTA     148
#define BB       2048
#define TSTEPS   512
#define PP       17
#define HH       50
#define GG       200         // 4*H gates
#define TT       544
#define XW       (TSTEPS*PP)
#define OUTW     (TT*PP)
#define KP       52          // padded hidden stride (floats)
#define XP       20          // padded input stride
#define NCF      12          // full 4-float chunks (k=0..47); tail k=48,49

// ---------------- smem layout (float offsets) ----------------
// Weight matrices: [12 full chunks][200][4] + [200][2] tail = 10000 floats each
#define OFF_W2    0          // Wih2 @0 (full 9600 + tail 400), Whh2 @10000
#define OFF_W3    20000
#define OFF_W1H   40000      // Whh1 (10000)
#define OFF_B2    50000      // 200
#define OFF_B3    50200      // 200
#define OFF_WLIN  50400      // 17*52 = 884
#define OFF_BLIN  51284      // 17 (+3 pad)
#define OFF_GS    51304      // 14*200 = 2800
#define OFF_HS1   54104      // 14*52
#define OFF_HS2   54832
#define OFF_HS3   55560
#define OFF_XS    56288      // 14*20
#define SMEM_FLOATS 56568    // 226,272 bytes

#define WTAIL_IH  9600       // tail offset inside each 10000-float matrix half
#define WHH_OFF   10000      // Whh half offset inside W2/W3 blocks

// ---------------- packed f32x2 helpers ----------------
__device__ __forceinline__ void ffma2(uint64_t& d, uint64_t a, uint64_t b) {
    asm("fma.rn.f32x2 %0, %1, %2, %0;" : "+l"(d) : "l"(a), "l"(b));
}
__device__ __forceinline__ uint64_t pack2(float lo, float hi) {
    uint64_t r;
    asm("mov.b64 %0, {%1, %2};" : "=l"(r) : "f"(lo), "f"(hi));
    return r;
}
__device__ __forceinline__ float hadd2(uint64_t v) {
    float lo, hi;
    asm("mov.b64 {%0, %1}, %2;" : "=f"(lo), "=f"(hi) : "l"(v));
    return lo + hi;
}

__device__ __forceinline__ float fsig(float x) {
    return __fdividef(1.0f, 1.0f + __expf(-x));
}
__device__ __forceinline__ float ftanh_(float x) {
    return 2.0f * __fdividef(1.0f, 1.0f + __expf(-2.0f * x)) - 1.0f;
}

extern __shared__ float sm[];

// layers 2/3 gates: conflict-free smem weights, packed-k FMA, 7-row split.
__device__ __forceinline__ void gates23(
    const float* __restrict__ W, const float* __restrict__ Hin,
    const float* __restrict__ Hsame, const float* __restrict__ Bsm,
    float* __restrict__ GS, int g, bool gok, int rbase)
{
    uint64_t acc[NBT];
    const float bg = Bsm[g];
#pragma unroll
    for (int r = 0; r < NBT; r++) acc[r] = pack2(bg, 0.f);

#pragma unroll
    for (int c = 0; c < NCF; c++) {
        ulonglong2 wx = *(const ulonglong2*)(W + c * 800 + g * 4);
        ulonglong2 wh = *(const ulonglong2*)(W + WHH_OFF + c * 800 + g * 4);
#pragma unroll
        for (int r = 0; r < NBT; r++) {
            ulonglong2 a = *(const ulonglong2*)(Hin   + (rbase + r) * KP + c * 4);
            ulonglong2 b = *(const ulonglong2*)(Hsame + (rbase + r) * KP + c * 4);
            ffma2(acc[r], wx.x, a.x);
            ffma2(acc[r], wx.y, a.y);
            ffma2(acc[r], wh.x, b.x);
            ffma2(acc[r], wh.y, b.y);
        }
    }
    // tail k = 48,49
    {
        uint64_t wxt = *(const uint64_t*)(W + WTAIL_IH + g * 2);
        uint64_t wht = *(const uint64_t*)(W + WHH_OFF + WTAIL_IH + g * 2);
#pragma unroll
        for (int r = 0; r < NBT; r++) {
            uint64_t a = *(const uint64_t*)(Hin   + (rbase + r) * KP + 48);
            uint64_t b = *(const uint64_t*)(Hsame + (rbase + r) * KP + 48);
            ffma2(acc[r], wxt, a);
            ffma2(acc[r], wht, b);
        }
    }
    if (gok) {
#pragma unroll
        for (int r = 0; r < NBT; r++) GS[(rbase + r) * GG + g] = hadd2(acc[r]);
    }
}

// LSTM pointwise: 2 items/thread cover NB*H = 700 outputs (448*2 = 896).
__device__ __forceinline__ void act_layer(
    const float* __restrict__ GS, float* __restrict__ Hdst,
    float (&c)[2], const int (&ar)[2], const int (&aj)[2], const bool (&av)[2])
{
#pragma unroll
    for (int q = 0; q < 2; q++) {
        if (av[q]) {
            int base = ar[q] * GG + aj[q];
            float xi = GS[base];
            float xf = GS[base + HH];
            float xg = GS[base + 2 * HH];
            float xo = GS[base + 3 * HH];
            float iv = fsig(xi), fv = fsig(xf), gv = ftanh_(xg), ov = fsig(xo);
            float cn = fmaf(fv, c[q], iv * gv);
            c[q] = cn;
            Hdst[ar[q] * KP + aj[q]] = ov * ftanh_(cn);
        }
    }
}

__global__ void __launch_bounds__(NTHREADS, 1)
lstm_forward(const float* __restrict__ x,
             const float* __restrict__ Wih1, const float* __restrict__ Whh1,
             const float* __restrict__ bih1, const float* __restrict__ bhh1,
             const float* __restrict__ Wih2, const float* __restrict__ Whh2,
             const float* __restrict__ bih2, const float* __restrict__ bhh2,
             const float* __restrict__ Wih3, const float* __restrict__ Whh3,
             const float* __restrict__ bih3, const float* __restrict__ bhh3,
             const float* __restrict__ Wlin, const float* __restrict__ blin,
             float* __restrict__ out)
{
    const int tid  = threadIdx.x;
    const int row0 = blockIdx.x * NB;

    const int  lt    = tid % 224;            // gate lane
    const bool gok   = (lt < GG);
    const int  g     = gok ? lt : 0;
    const int  rbase = (tid / 224) * NBT;    // 0 or 7

    // ---- cooperative weight repack (full chunks, k=0..47) ----
    for (int idx = tid; idx < NCF * GG * 4; idx += NTHREADS) {
        int c   = idx / 800;
        int rem = idx - c * 800;
        int gg  = rem >> 2;
        int j   = rem & 3;
        int k   = c * 4 + j;
        int src = gg * HH + k;
        sm[OFF_W2           + idx] = Wih2[src];
        sm[OFF_W2 + WHH_OFF + idx] = Whh2[src];
        sm[OFF_W3           + idx] = Wih3[src];
        sm[OFF_W3 + WHH_OFF + idx] = Whh3[src];
        sm[OFF_W1H          + idx] = Whh1[src];
    }
    // tails k = 48,49
    for (int idx = tid; idx < GG * 2; idx += NTHREADS) {
        int gg = idx >> 1;
        int k  = 48 + (idx & 1);
        int src = gg * HH + k;
        sm[OFF_W2 + WTAIL_IH           + idx] = Wih2[src];
        sm[OFF_W2 + WHH_OFF + WTAIL_IH + idx] = Whh2[src];
        sm[OFF_W3 + WTAIL_IH           + idx] = Wih3[src];
        sm[OFF_W3 + WHH_OFF + WTAIL_IH + idx] = Whh3[src];
        sm[OFF_W1H + WTAIL_IH          + idx] = Whh1[src];
    }
    for (int idx = tid; idx < GG; idx += NTHREADS) {
        sm[OFF_B2 + idx] = bih2[idx] + bhh2[idx];
        sm[OFF_B3 + idx] = bih3[idx] + bhh3[idx];
    }
    for (int idx = tid; idx < PP * KP; idx += NTHREADS) {
        int p = idx / KP, k = idx - p * KP;
        sm[OFF_WLIN + idx] = (k < HH) ? Wlin[p * HH + k] : 0.f;
    }
    if (tid < PP) sm[OFF_BLIN + tid] = blin[tid];
    for (int idx = tid; idx < 3 * NB * KP; idx += NTHREADS) sm[OFF_HS1 + idx] = 0.f;
    for (int idx = tid; idx < NB * XP; idx += NTHREADS)     sm[OFF_XS  + idx] = 0.f;

    // ---- layer-1 input weights in registers as packed pairs (17 real) ----
    uint64_t w1x2[XP / 2];
    float bg1;
    {
#pragma unroll
        for (int i = 0; i < XP / 2; i++) {
            int k0 = 2 * i, k1 = 2 * i + 1;
            float a = (k0 < PP) ? Wih1[g * PP + k0] : 0.f;
            float b = (k1 < PP) ? Wih1[g * PP + k1] : 0.f;
            w1x2[i] = pack2(a, b);
        }
        bg1 = bih1[g] + bhh1[g];
    }

    // ---- per-thread work-item maps ----
    int ar[2], aj[2]; bool av[2];              // activation items (700)
#pragma unroll
    for (int q = 0; q < 2; q++) {
        int it = tid + q * NTHREADS;
        av[q] = (it < NB * HH);
        int r = it / HH;
        ar[q] = r; aj[q] = it - r * HH;
    }
    const bool hv = (tid < NB * PP);           // head / x-load item (238)
    const int  hr = hv ? tid / PP : 0;
    const int  hp = hv ? tid - hr * PP : 0;

    float c1[2] = {0.f, 0.f};
    float c2[2] = {0.f, 0.f};
    float c3[2] = {0.f, 0.f};

    // ---- prefetch x for t=0 ----
    float xreg = 0.f;
    if (hv) {
        int brow = row0 + hr;
        if (brow < BB) xreg = x[(size_t)brow * XW + hp];
    }
    __syncthreads();

    // ================= time loop =================
    for (int t = 0; t < TT; t++) {
        if (t < TSTEPS) {
            if (hv) sm[OFF_XS + hr * XP + hp] = xreg;
        }
        __syncthreads();                                   // S0: XS ready

        if (t + 1 < TSTEPS && hv) {
            int brow = row0 + hr;
            xreg = (brow < BB) ? x[(size_t)brow * XW + (t + 1) * PP + hp] : 0.f;
        }

        // ---- layer 1 gates ----
        {
            uint64_t acc[NBT];
#pragma unroll
            for (int r = 0; r < NBT; r++) acc[r] = pack2(bg1, 0.f);
#pragma unroll
            for (int c = 0; c < XP / 4; c++) {
#pragma unroll
                for (int r = 0; r < NBT; r++) {
                    ulonglong2 v = *(const ulonglong2*)(sm + OFF_XS + (rbase + r) * XP + c * 4);
                    ffma2(acc[r], w1x2[2 * c    ], v.x);
                    ffma2(acc[r], w1x2[2 * c + 1], v.y);
                }
            }
#pragma unroll
            for (int c = 0; c < NCF; c++) {
                ulonglong2 wh = *(const ulonglong2*)(sm + OFF_W1H + c * 800 + g * 4);
#pragma unroll
                for (int r = 0; r < NBT; r++) {
                    ulonglong2 v = *(const ulonglong2*)(sm + OFF_HS1 + (rbase + r) * KP + c * 4);
                    ffma2(acc[r], wh.x, v.x);
                    ffma2(acc[r], wh.y, v.y);
                }
            }
            {
                uint64_t wht = *(const uint64_t*)(sm + OFF_W1H + WTAIL_IH + g * 2);
#pragma unroll
                for (int r = 0; r < NBT; r++) {
                    uint64_t v = *(const uint64_t*)(sm + OFF_HS1 + (rbase + r) * KP + 48);
                    ffma2(acc[r], wht, v);
                }
            }
            if (gok) {
#pragma unroll
                for (int r = 0; r < NBT; r++) sm[OFF_GS + (rbase + r) * GG + g] = hadd2(acc[r]);
            }
        }
        __syncthreads();                                   // S1
        act_layer(sm + OFF_GS, sm + OFF_HS1, c1, ar, aj, av);
        __syncthreads();                                   // S2

        gates23(sm + OFF_W2, sm + OFF_HS1, sm + OFF_HS2, sm + OFF_B2,
                sm + OFF_GS, g, gok, rbase);
        __syncthreads();                                   // S3
        act_layer(sm + OFF_GS, sm + OFF_HS2, c2, ar, aj, av);
        __syncthreads();                                   // S4

        gates23(sm + OFF_W3, sm + OFF_HS2, sm + OFF_HS3, sm + OFF_B3,
                sm + OFF_GS, g, gok, rbase);
        __syncthreads();                                   // S5
        act_layer(sm + OFF_GS, sm + OFF_HS3, c3, ar, aj, av);
        __syncthreads();                                   // S6

        // ---- linear head + output store (+ autoregressive feedback) ----
        if (hv) {
            uint64_t acc = pack2(sm[OFF_BLIN + hp], 0.f);
#pragma unroll
            for (int c = 0; c < KP / 4; c++) {
                ulonglong2 w = *(const ulonglong2*)(sm + OFF_WLIN + hp * KP + c * 4);
                ulonglong2 h = *(const ulonglong2*)(sm + OFF_HS3  + hr * KP + c * 4);
                ffma2(acc, w.x, h.x);
                ffma2(acc, w.y, h.y);
            }
            float res = hadd2(acc);
            int brow = row0 + hr;
            if (brow < BB) out[(size_t)brow * OUTW + t * PP + hp] = res;
            if (t >= TSTEPS - 1) sm[OFF_XS + hr * XP + hp] = res;
        }
        // loop-top S0 orders XS feedback vs. next layer-1 reads
    }
}

extern "C" void kernel_launch(void* const* d_in, const int* in_sizes, int n_in,
                              void* d_out, int out_size)
{
    const float* x    = (const float*)d_in[0];
    const float* Wih1 = (const float*)d_in[1];
    const float* Whh1 = (const float*)d_in[2];
    const float* bih1 = (const float*)d_in[3];
    const float* bhh1 = (const float*)d_in[4];
    const float* Wih2 = (const float*)d_in[5];
    const float* Whh2 = (const float*)d_in[6];
    const float* bih2 = (const float*)d_in[7];
    const float* bhh2 = (const float*)d_in[8];
    const float* Wih3 = (const float*)d_in[9];
    const float* Whh3 = (const float*)d_in[10];
    const float* bih3 = (const float*)d_in[11];
    const float* bhh3 = (const float*)d_in[12];
    const float* Wlin = (const float*)d_in[13];
    const float* blin = (const float*)d_in[14];
    float* out = (float*)d_out;

    const size_t smem = (size_t)SMEM_FLOATS * sizeof(float);
    cudaFuncSetAttribute(lstm_forward,
                         cudaFuncAttributeMaxDynamicSharedMemorySize, (int)smem);
    lstm_forward<<<NCTA, NTHREADS, smem>>>(
        x, Wih1, Whh1, bih1, bhh1, Wih2, Whh2, bih2, bhh2,
        Wih3, Whh3, bih3, bhh3, Wlin, blin, out);
}

// round 11
// speedup vs baseline: 1.4585x; 1.0887x over previous
#include <cuda_runtime.h>
#include <cstdint>

// ---------------- problem constants ----------------
#define NTHREADS 224
#define NB       14          // batch rows per CTA
#define NCTA     148
#define BB       2048
#define TSTEPS   512
#define PP       17
#define HH       50
#define GG       200         // 4*H gates
#define TT       544
#define XW       (TSTEPS*PP)
#define OUTW     (TT*PP)
#define KP       52          // padded hidden stride (floats)
#define XP       20          // padded input stride
#define NCF      12          // full 4-float chunks (k=0..47); tail k=48,49

// ---------------- smem layout (float offsets) ----------------
// W2/W3: [12 chunks][200][4] + [200][2] tail per matrix half (10000 each)
#define OFF_W2    0          // Wih2 @0, Whh2 @+10000
#define OFF_W3    20000
#define OFF_B2    40000      // 200
#define OFF_B3    40200      // 200
#define OFF_WLIN  40400      // 17*52 = 884
#define OFF_BLIN  41284      // 17 (+3 pad)
#define OFF_GS1   41304      // 14*200
#define OFF_GS2   44104
#define OFF_GS3   46904
#define OFF_HS1   49704      // 14*52
#define OFF_HS2   50432
#define OFF_HS3   51160
#define OFF_XS    51888      // 14*20
#define SMEM_FLOATS 52168    // 208,672 bytes

#define WTAIL_IH  9600
#define WHH_OFF   10000

// ---------------- packed f32x2 helpers ----------------
__device__ __forceinline__ void ffma2(uint64_t& d, uint64_t a, uint64_t b) {
    asm("fma.rn.f32x2 %0, %1, %2, %0;" : "+l"(d) : "l"(a), "l"(b));
}
__device__ __forceinline__ uint64_t pack2(float lo, float hi) {
    uint64_t r;
    asm("mov.b64 %0, {%1, %2};" : "=l"(r) : "f"(lo), "f"(hi));
    return r;
}
__device__ __forceinline__ float hadd2(uint64_t v) {
    float lo, hi;
    asm("mov.b64 {%0, %1}, %2;" : "=f"(lo), "=f"(hi) : "l"(v));
    return lo + hi;
}

__device__ __forceinline__ float fsig(float x) {
    return __fdividef(1.0f, 1.0f + __expf(-x));
}
__device__ __forceinline__ float ftanh_(float x) {
    return 2.0f * __fdividef(1.0f, 1.0f + __expf(-2.0f * x)) - 1.0f;
}

extern __shared__ float sm[];

// layers 2/3 gates: conflict-free smem weights, packed-k FMA, all 14 rows.
__device__ __forceinline__ void gates23(
    const float* __restrict__ W, const float* __restrict__ Hin,
    const float* __restrict__ Hsame, const float* __restrict__ Bsm,
    float* __restrict__ GS, int g, bool gok)
{
    uint64_t acc[NB];
    const float bg = Bsm[g];
#pragma unroll
    for (int r = 0; r < NB; r++) acc[r] = pack2(bg, 0.f);

#pragma unroll
    for (int c = 0; c < NCF; c++) {
        ulonglong2 wx = *(const ulonglong2*)(W + c * 800 + g * 4);
        ulonglong2 wh = *(const ulonglong2*)(W + WHH_OFF + c * 800 + g * 4);
#pragma unroll
        for (int r = 0; r < NB; r++) {
            ulonglong2 a = *(const ulonglong2*)(Hin   + r * KP + c * 4);
            ulonglong2 b = *(const ulonglong2*)(Hsame + r * KP + c * 4);
            ffma2(acc[r], wx.x, a.x);
            ffma2(acc[r], wx.y, a.y);
            ffma2(acc[r], wh.x, b.x);
            ffma2(acc[r], wh.y, b.y);
        }
    }
    {   // tail k = 48,49
        uint64_t wxt = *(const uint64_t*)(W + WTAIL_IH + g * 2);
        uint64_t wht = *(const uint64_t*)(W + WHH_OFF + WTAIL_IH + g * 2);
#pragma unroll
        for (int r = 0; r < NB; r++) {
            uint64_t a = *(const uint64_t*)(Hin   + r * KP + 48);
            uint64_t b = *(const uint64_t*)(Hsame + r * KP + 48);
            ffma2(acc[r], wxt, a);
            ffma2(acc[r], wht, b);
        }
    }
    if (gok) {
#pragma unroll
        for (int r = 0; r < NB; r++) GS[r * GG + g] = hadd2(acc[r]);
    }
}

// LSTM pointwise: 4 items/thread cover 700 outputs.
__device__ __forceinline__ void act_layer(
    const float* __restrict__ GS, float* __restrict__ Hdst,
    float (&c)[4], const int (&ar)[4], const int (&aj)[4], const bool (&av)[4])
{
#pragma unroll
    for (int q = 0; q < 4; q++) {
        if (av[q]) {
            int base = ar[q] * GG + aj[q];
            float xi = GS[base];
            float xf = GS[base + HH];
            float xg = GS[base + 2 * HH];
            float xo = GS[base + 3 * HH];
            float iv = fsig(xi), fv = fsig(xf), gv = ftanh_(xg), ov = fsig(xo);
            float cn = fmaf(fv, c[q], iv * gv);
            c[q] = cn;
            Hdst[ar[q] * KP + aj[q]] = ov * ftanh_(cn);
        }
    }
}

__global__ void __launch_bounds__(NTHREADS, 1)
lstm_forward(const float* __restrict__ x,
             const float* __restrict__ Wih1, const float* __restrict__ Whh1,
             const float* __restrict__ bih1, const float* __restrict__ bhh1,
             const float* __restrict__ Wih2, const float* __restrict__ Whh2,
             const float* __restrict__ bih2, const float* __restrict__ bhh2,
             const float* __restrict__ Wih3, const float* __restrict__ Whh3,
             const float* __restrict__ bih3, const float* __restrict__ bhh3,
             const float* __restrict__ Wlin, const float* __restrict__ blin,
             float* __restrict__ out)
{
    const int tid  = threadIdx.x;
    const int row0 = blockIdx.x * NB;

    const bool gok = (tid < GG);
    const int  g   = gok ? tid : 0;

    // ---- cooperative weight repack W2/W3 (conflict-free [c][g][4]) ----
    for (int idx = tid; idx < NCF * GG * 4; idx += NTHREADS) {
        int c   = idx / 800;
        int rem = idx - c * 800;
        int gg  = rem >> 2;
        int j   = rem & 3;
        int src = gg * HH + c * 4 + j;
        sm[OFF_W2           + idx] = Wih2[src];
        sm[OFF_W2 + WHH_OFF + idx] = Whh2[src];
        sm[OFF_W3           + idx] = Wih3[src];
        sm[OFF_W3 + WHH_OFF + idx] = Whh3[src];
    }
    for (int idx = tid; idx < GG * 2; idx += NTHREADS) {
        int gg = idx >> 1;
        int src = gg * HH + 48 + (idx & 1);
        sm[OFF_W2 + WTAIL_IH           + idx] = Wih2[src];
        sm[OFF_W2 + WHH_OFF + WTAIL_IH + idx] = Whh2[src];
        sm[OFF_W3 + WTAIL_IH           + idx] = Wih3[src];
        sm[OFF_W3 + WHH_OFF + WTAIL_IH + idx] = Whh3[src];
    }
    for (int idx = tid; idx < GG; idx += NTHREADS) {
        sm[OFF_B2 + idx] = bih2[idx] + bhh2[idx];
        sm[OFF_B3 + idx] = bih3[idx] + bhh3[idx];
    }
    for (int idx = tid; idx < PP * KP; idx += NTHREADS) {
        int p = idx / KP, k = idx - p * KP;
        sm[OFF_WLIN + idx] = (k < HH) ? Wlin[p * HH + k] : 0.f;
    }
    if (tid < PP) sm[OFF_BLIN + tid] = blin[tid];
    for (int idx = tid; idx < 3 * NB * KP; idx += NTHREADS) sm[OFF_HS1 + idx] = 0.f;
    for (int idx = tid; idx < NB * XP; idx += NTHREADS)     sm[OFF_XS  + idx] = 0.f;

    // ---- layer-1 weights in registers as packed k-pairs ----
    uint64_t w1x2[XP / 2];   // 10 pairs (17 real)
    uint64_t w1h2[KP / 2];   // 26 pairs (50 real)
    float bg1;
    {
#pragma unroll
        for (int i = 0; i < XP / 2; i++) {
            int k0 = 2 * i, k1 = 2 * i + 1;
            float a = (k0 < PP) ? Wih1[g * PP + k0] : 0.f;
            float b = (k1 < PP) ? Wih1[g * PP + k1] : 0.f;
            w1x2[i] = pack2(a, b);
        }
#pragma unroll
        for (int i = 0; i < KP / 2; i++) {
            int k0 = 2 * i, k1 = 2 * i + 1;
            float a = (k0 < HH) ? Whh1[g * HH + k0] : 0.f;
            float b = (k1 < HH) ? Whh1[g * HH + k1] : 0.f;
            w1h2[i] = pack2(a, b);
        }
        bg1 = bih1[g] + bhh1[g];
    }

    // ---- per-thread work-item maps ----
    int ar[4], aj[4]; bool av[4];              // activation items (700)
#pragma unroll
    for (int q = 0; q < 4; q++) {
        int it = tid + q * NTHREADS;
        av[q] = (it < NB * HH);
        int r = it / HH;
        ar[q] = r; aj[q] = it - r * HH;
    }
    int orr[2], op[2]; bool ov[2];             // head / x-load items (238)
#pragma unroll
    for (int q = 0; q < 2; q++) {
        int it = tid + q * NTHREADS;
        ov[q] = (it < NB * PP);
        int r = it / PP;
        orr[q] = r; op[q] = it - r * PP;
    }
    float c1[4] = {0.f,0.f,0.f,0.f};
    float c2[4] = {0.f,0.f,0.f,0.f};
    float c3[4] = {0.f,0.f,0.f,0.f};

    // ---- stage XS = x(t=0), prefetch xreg = x(t=1) ----
    float xreg[2] = {0.f, 0.f};
#pragma unroll
    for (int q = 0; q < 2; q++) {
        if (ov[q]) {
            int brow = row0 + orr[q];
            if (brow < BB) {
                sm[OFF_XS + orr[q] * XP + op[q]] = x[(size_t)brow * XW + op[q]];
                xreg[q] = x[(size_t)brow * XW + PP + op[q]];
            } else {
                sm[OFF_XS + orr[q] * XP + op[q]] = 0.f;
            }
        }
    }
    __syncthreads();

    // ================= pipelined teacher-forced loop =================
    // iteration i: L1@t=i, L2@t=i-1, L3@t=i-2, head@t=i-3
    for (int i = 0; i < TSTEPS + 3; i++) {
        const bool doL1 = (i < TSTEPS);
        const bool doL2 = (i >= 1) && (i < TSTEPS + 1);
        const bool doL3 = (i >= 2) && (i < TSTEPS + 2);
        const bool doHd = (i >= 3);
        const int  th   = i - 3;

        // ---------- Phase A: all gates + head ----------
        if (doL1) {
            uint64_t acc[NB];
#pragma unroll
            for (int r = 0; r < NB; r++) acc[r] = pack2(bg1, 0.f);
#pragma unroll
            for (int c = 0; c < XP / 4; c++) {
#pragma unroll
                for (int r = 0; r < NB; r++) {
                    ulonglong2 v = *(const ulonglong2*)(sm + OFF_XS + r * XP + c * 4);
                    ffma2(acc[r], w1x2[2 * c    ], v.x);
                    ffma2(acc[r], w1x2[2 * c + 1], v.y);
                }
            }
#pragma unroll
            for (int c = 0; c < KP / 4; c++) {
#pragma unroll
                for (int r = 0; r < NB; r++) {
                    ulonglong2 v = *(const ulonglong2*)(sm + OFF_HS1 + r * KP + c * 4);
                    ffma2(acc[r], w1h2[2 * c    ], v.x);
                    ffma2(acc[r], w1h2[2 * c + 1], v.y);
                }
            }
            if (gok) {
#pragma unroll
                for (int r = 0; r < NB; r++) sm[OFF_GS1 + r * GG + g] = hadd2(acc[r]);
            }
        }
        if (doL2)
            gates23(sm + OFF_W2, sm + OFF_HS1, sm + OFF_HS2, sm + OFF_B2,
                    sm + OFF_GS2, g, gok);
        if (doL3)
            gates23(sm + OFF_W3, sm + OFF_HS2, sm + OFF_HS3, sm + OFF_B3,
                    sm + OFF_GS3, g, gok);
        if (doHd) {
#pragma unroll
            for (int q = 0; q < 2; q++) {
                if (ov[q]) {
                    int r = orr[q], p = op[q];
                    uint64_t acc = pack2(sm[OFF_BLIN + p], 0.f);
#pragma unroll
                    for (int c = 0; c < KP / 4; c++) {
                        ulonglong2 w = *(const ulonglong2*)(sm + OFF_WLIN + p * KP + c * 4);
                        ulonglong2 h = *(const ulonglong2*)(sm + OFF_HS3  + r * KP + c * 4);
                        ffma2(acc, w.x, h.x);
                        ffma2(acc, w.y, h.y);
                    }
                    float res = hadd2(acc);
                    int brow = row0 + r;
                    if (brow < BB) out[(size_t)brow * OUTW + th * PP + p] = res;
                    // last teacher-forced output feeds x(TSTEPS) for the tail loop
                    if (th == TSTEPS - 1) sm[OFF_XS + r * XP + p] = res;
                }
            }
        }
        __syncthreads();                       // SA: gates/head done

        // ---------- Phase B: activations + input staging ----------
        if (doL1) act_layer(sm + OFF_GS1, sm + OFF_HS1, c1, ar, aj, av);
        if (doL2) act_layer(sm + OFF_GS2, sm + OFF_HS2, c2, ar, aj, av);
        if (doL3) act_layer(sm + OFF_GS3, sm + OFF_HS3, c3, ar, aj, av);
        if (i + 1 < TSTEPS) {
#pragma unroll
            for (int q = 0; q < 2; q++)
                if (ov[q]) sm[OFF_XS + orr[q] * XP + op[q]] = xreg[q];
            if (i + 2 < TSTEPS) {
#pragma unroll
                for (int q = 0; q < 2; q++) {
                    if (ov[q]) {
                        int brow = row0 + orr[q];
                        xreg[q] = (brow < BB)
                            ? x[(size_t)brow * XW + (i + 2) * PP + op[q]] : 0.f;
                    }
                }
            }
        }
        __syncthreads();                       // SB: H/X ready for next iter
    }

    // ================= sequential autoregressive tail =================
    for (int t = TSTEPS; t < TT; t++) {
        // XS holds out(t-1) = x(t) (written by previous head, barrier-ordered)
        {   // L1 gates
            uint64_t acc[NB];
#pragma unroll
            for (int r = 0; r < NB; r++) acc[r] = pack2(bg1, 0.f);
#pragma unroll
            for (int c = 0; c < XP / 4; c++) {
#pragma unroll
                for (int r = 0; r < NB; r++) {
                    ulonglong2 v = *(const ulonglong2*)(sm + OFF_XS + r * XP + c * 4);
                    ffma2(acc[r], w1x2[2 * c    ], v.x);
                    ffma2(acc[r], w1x2[2 * c + 1], v.y);
                }
            }
#pragma unroll
            for (int c = 0; c < KP / 4; c++) {
#pragma unroll
                for (int r = 0; r < NB; r++) {
                    ulonglong2 v = *(const ulonglong2*)(sm + OFF_HS1 + r * KP + c * 4);
                    ffma2(acc[r], w1h2[2 * c    ], v.x);
                    ffma2(acc[r], w1h2[2 * c + 1], v.y);
                }
            }
            if (gok) {
#pragma unroll
                for (int r = 0; r < NB; r++) sm[OFF_GS1 + r * GG + g] = hadd2(acc[r]);
            }
        }
        __syncthreads();
        act_layer(sm + OFF_GS1, sm + OFF_HS1, c1, ar, aj, av);
        __syncthreads();
        gates23(sm + OFF_W2, sm + OFF_HS1, sm + OFF_HS2, sm + OFF_B2,
                sm + OFF_GS2, g, gok);
        __syncthreads();
        act_layer(sm + OFF_GS2, sm + OFF_HS2, c2, ar, aj, av);
        __syncthreads();
        gates23(sm + OFF_W3, sm + OFF_HS2, sm + OFF_HS3, sm + OFF_B3,
                sm + OFF_GS3, g, gok);
        __syncthreads();
        act_layer(sm + OFF_GS3, sm + OFF_HS3, c3, ar, aj, av);
        __syncthreads();
        // head: out(t) + feed XS for t+1
#pragma unroll
        for (int q = 0; q < 2; q++) {
            if (ov[q]) {
                int r = orr[q], p = op[q];
                uint64_t acc = pack2(sm[OFF_BLIN + p], 0.f);
#pragma unroll
                for (int c = 0; c < KP / 4; c++) {
                    ulonglong2 w = *(const ulonglong2*)(sm + OFF_WLIN + p * KP + c * 4);
                    ulonglong2 h = *(const ulonglong2*)(sm + OFF_HS3  + r * KP + c * 4);
                    ffma2(acc, w.x, h.x);
                    ffma2(acc, w.y, h.y);
                }
                float res = hadd2(acc);
                int brow = row0 + r;
                if (brow < BB) out[(size_t)brow * OUTW + t * PP + p] = res;
                sm[OFF_XS + r * XP + p] = res;
            }
        }
        __syncthreads();                       // XS ready for next t
    }
}

extern "C" void kernel_launch(void* const* d_in, const int* in_sizes, int n_in,
                              void* d_out, int out_size)
{
    const float* x    = (const float*)d_in[0];
    const float* Wih1 = (const float*)d_in[1];
    const float* Whh1 = (const float*)d_in[2];
    const float* bih1 = (const float*)d_in[3];
    const float* bhh1 = (const float*)d_in[4];
    const float* Wih2 = (const float*)d_in[5];
    const float* Whh2 = (const float*)d_in[6];
    const float* bih2 = (const float*)d_in[7];
    const float* bhh2 = (const float*)d_in[8];
    const float* Wih3 = (const float*)d_in[9];
    const float* Whh3 = (const float*)d_in[10];
    const float* bih3 = (const float*)d_in[11];
    const float* bhh3 = (const float*)d_in[12];
    const float* Wlin = (const float*)d_in[13];
    const float* blin = (const float*)d_in[14];
    float* out = (float*)d_out;

    const size_t smem = (size_t)SMEM_FLOATS * sizeof(float);
    cudaFuncSetAttribute(lstm_forward,
                         cudaFuncAttributeMaxDynamicSharedMemorySize, (int)smem);
    lstm_forward<<<NCTA, NTHREADS, smem>>>(
        x, Wih1, Whh1, bih1, bhh1, Wih2, Whh2, bih2, bhh2,
        Wih3, Whh3, bih3, bhh3, Wlin, blin, out);
}

// round 12
// speedup vs baseline: 1.5727x; 1.0783x over previous
#include <cuda_runtime.h>
#include <cstdint>

// ---------------- problem constants ----------------
#define NTHREADS 224
#define NB       14          // batch rows per CTA
#define NBT      7           // rows per L2/L3 thread (row split)
#define NCTA     148
#define BB       2048
#define TSTEPS   512
#define PP       17
#define HH       50
#define GG       200         // 4*H gates
#define TT       544
#define XW       (TSTEPS*PP)
#define OUTW     (TT*PP)
#define KP       52          // padded hidden stride (floats)
#define XP       20          // padded input stride

// ---------------- smem layout (float offsets) ----------------
// W2/W3 packed for 2-gate tiling: [26 kpairs][100 gatepairs][4]:
//   {W[2p][2kp], W[2p][2kp+1], W[2p+1][2kp], W[2p+1][2kp+1]}, zero-pad k>=50.
// Each matrix half = 26*100*4 = 10400 floats. Wih at +0, Whh at +10400.
#define OFF_WP2   0          // 20800
#define OFF_WP3   20800      // 20800
#define OFF_B2    41600      // 200
#define OFF_B3    41800      // 200
#define OFF_WLIN  42000      // 17*52 = 884
#define OFF_BLIN  42884      // 17 (+3 pad)
#define OFF_GS1   42904      // 14*200
#define OFF_GS2   45704
#define OFF_GS3   48504
#define OFF_HS1   51304      // 14*52
#define OFF_HS2   52032
#define OFF_HS3   52760
#define OFF_XS    53488      // 14*20
#define SMEM_FLOATS 53768    // 215,072 bytes

#define WHH_OFF   10400      // Whh half offset inside a WP block

// ---------------- packed f32x2 helpers ----------------
__device__ __forceinline__ void ffma2(uint64_t& d, uint64_t a, uint64_t b) {
    asm("fma.rn.f32x2 %0, %1, %2, %0;" : "+l"(d) : "l"(a), "l"(b));
}
__device__ __forceinline__ uint64_t pack2(float lo, float hi) {
    uint64_t r;
    asm("mov.b64 %0, {%1, %2};" : "=l"(r) : "f"(lo), "f"(hi));
    return r;
}
__device__ __forceinline__ float hadd2(uint64_t v) {
    float lo, hi;
    asm("mov.b64 {%0, %1}, %2;" : "=f"(lo), "=f"(hi) : "l"(v));
    return lo + hi;
}

__device__ __forceinline__ float fsig(float x) {
    return __fdividef(1.0f, 1.0f + __expf(-x));
}
__device__ __forceinline__ float ftanh_(float x) {
    return 2.0f * __fdividef(1.0f, 1.0f + __expf(-2.0f * x)) - 1.0f;
}

extern __shared__ float sm[];

// layers 2/3 gates: 2 gates x 7 rows per thread, 2g-packed weights.
// Accumulation order per gate identical to the 1gx14r version.
__device__ __forceinline__ void gates23(
    const float* __restrict__ Wp, const float* __restrict__ Hin,
    const float* __restrict__ Hsame, const float* __restrict__ Bsm,
    float* __restrict__ GS, int p, bool pok, int rbase)
{
    uint64_t accA[NBT], accB[NBT];
    const float bgA = Bsm[2 * p];
    const float bgB = Bsm[2 * p + 1];
#pragma unroll
    for (int r = 0; r < NBT; r++) {
        accA[r] = pack2(bgA, 0.f);
        accB[r] = pack2(bgB, 0.f);
    }

#pragma unroll
    for (int ch = 0; ch < 13; ch++) {       // 4-k chunks; kpairs 2ch, 2ch+1
        ulonglong2 wx0 = *(const ulonglong2*)(Wp + (2 * ch    ) * 400 + p * 4);
        ulonglong2 wx1 = *(const ulonglong2*)(Wp + (2 * ch + 1) * 400 + p * 4);
        ulonglong2 wh0 = *(const ulonglong2*)(Wp + WHH_OFF + (2 * ch    ) * 400 + p * 4);
        ulonglong2 wh1 = *(const ulonglong2*)(Wp + WHH_OFF + (2 * ch + 1) * 400 + p * 4);
#pragma unroll
        for (int r = 0; r < NBT; r++) {
            ulonglong2 a = *(const ulonglong2*)(Hin   + (rbase + r) * KP + ch * 4);
            ulonglong2 b = *(const ulonglong2*)(Hsame + (rbase + r) * KP + ch * 4);
            ffma2(accA[r], wx0.x, a.x);
            ffma2(accA[r], wx1.x, a.y);
            ffma2(accB[r], wx0.y, a.x);
            ffma2(accB[r], wx1.y, a.y);
            ffma2(accA[r], wh0.x, b.x);
            ffma2(accA[r], wh1.x, b.y);
            ffma2(accB[r], wh0.y, b.x);
            ffma2(accB[r], wh1.y, b.y);
        }
    }
    if (pok) {
#pragma unroll
        for (int r = 0; r < NBT; r++) {
            float resA = hadd2(accA[r]);
            float resB = hadd2(accB[r]);
            *(uint64_t*)(GS + (rbase + r) * GG + 2 * p) = pack2(resA, resB);
        }
    }
}

// LSTM pointwise: 4 items/thread cover 700 outputs.
__device__ __forceinline__ void act_layer(
    const float* __restrict__ GS, float* __restrict__ Hdst,
    float (&c)[4], const int (&ar)[4], const int (&aj)[4], const bool (&av)[4])
{
#pragma unroll
    for (int q = 0; q < 4; q++) {
        if (av[q]) {
            int base = ar[q] * GG + aj[q];
            float xi = GS[base];
            float xf = GS[base + HH];
            float xg = GS[base + 2 * HH];
            float xo = GS[base + 3 * HH];
            float iv = fsig(xi), fv = fsig(xf), gv = ftanh_(xg), ov = fsig(xo);
            float cn = fmaf(fv, c[q], iv * gv);
            c[q] = cn;
            Hdst[ar[q] * KP + aj[q]] = ov * ftanh_(cn);
        }
    }
}

__global__ void __launch_bounds__(NTHREADS, 1)
lstm_forward(const float* __restrict__ x,
             const float* __restrict__ Wih1, const float* __restrict__ Whh1,
             const float* __restrict__ bih1, const float* __restrict__ bhh1,
             const float* __restrict__ Wih2, const float* __restrict__ Whh2,
             const float* __restrict__ bih2, const float* __restrict__ bhh2,
             const float* __restrict__ Wih3, const float* __restrict__ Whh3,
             const float* __restrict__ bih3, const float* __restrict__ bhh3,
             const float* __restrict__ Wlin, const float* __restrict__ blin,
             float* __restrict__ out)
{
    const int tid  = threadIdx.x;
    const int row0 = blockIdx.x * NB;

    // L1 map: one gate x 14 rows
    const bool gok = (tid < GG);
    const int  g   = gok ? tid : 0;
    // L2/L3 map: gate-pair x 7 rows
    const int  p2     = tid % 112;
    const bool pok    = (p2 < 100);
    const int  pp2    = pok ? p2 : 0;
    const int  rbase2 = (tid / 112) * NBT;   // 0 or 7

    // ---- cooperative weight repack: [kp][pair][4] with zero-pad k>=50 ----
    for (int idx = tid; idx < 26 * 100 * 4; idx += NTHREADS) {
        int kp  = idx / 400;
        int rem = idx - kp * 400;
        int pr  = rem >> 2;
        int qd  = rem & 3;
        int gg  = 2 * pr + (qd >> 1);
        int k   = 2 * kp + (qd & 1);
        bool v  = (k < HH);
        int src = gg * HH + k;
        sm[OFF_WP2           + idx] = v ? Wih2[src] : 0.f;
        sm[OFF_WP2 + WHH_OFF + idx] = v ? Whh2[src] : 0.f;
        sm[OFF_WP3           + idx] = v ? Wih3[src] : 0.f;
        sm[OFF_WP3 + WHH_OFF + idx] = v ? Whh3[src] : 0.f;
    }
    for (int idx = tid; idx < GG; idx += NTHREADS) {
        sm[OFF_B2 + idx] = bih2[idx] + bhh2[idx];
        sm[OFF_B3 + idx] = bih3[idx] + bhh3[idx];
    }
    for (int idx = tid; idx < PP * KP; idx += NTHREADS) {
        int p = idx / KP, k = idx - p * KP;
        sm[OFF_WLIN + idx] = (k < HH) ? Wlin[p * HH + k] : 0.f;
    }
    if (tid < PP) sm[OFF_BLIN + tid] = blin[tid];
    for (int idx = tid; idx < 3 * NB * KP; idx += NTHREADS) sm[OFF_HS1 + idx] = 0.f;
    for (int idx = tid; idx < NB * XP; idx += NTHREADS)     sm[OFF_XS  + idx] = 0.f;

    // ---- layer-1 weights in registers as packed k-pairs ----
    uint64_t w1x2[XP / 2];   // 10 pairs (17 real)
    uint64_t w1h2[KP / 2];   // 26 pairs (50 real)
    float bg1;
    {
#pragma unroll
        for (int i = 0; i < XP / 2; i++) {
            int k0 = 2 * i, k1 = 2 * i + 1;
            float a = (k0 < PP) ? Wih1[g * PP + k0] : 0.f;
            float b = (k1 < PP) ? Wih1[g * PP + k1] : 0.f;
            w1x2[i] = pack2(a, b);
        }
#pragma unroll
        for (int i = 0; i < KP / 2; i++) {
            int k0 = 2 * i, k1 = 2 * i + 1;
            float a = (k0 < HH) ? Whh1[g * HH + k0] : 0.f;
            float b = (k1 < HH) ? Whh1[g * HH + k1] : 0.f;
            w1h2[i] = pack2(a, b);
        }
        bg1 = bih1[g] + bhh1[g];
    }

    // ---- per-thread work-item maps ----
    int ar[4], aj[4]; bool av[4];              // activation items (700)
#pragma unroll
    for (int q = 0; q < 4; q++) {
        int it = tid + q * NTHREADS;
        av[q] = (it < NB * HH);
        int r = it / HH;
        ar[q] = r; aj[q] = it - r * HH;
    }
    int orr[2], op[2]; bool ov[2];             // head / x-load items (238)
#pragma unroll
    for (int q = 0; q < 2; q++) {
        int it = tid + q * NTHREADS;
        ov[q] = (it < NB * PP);
        int r = it / PP;
        orr[q] = r; op[q] = it - r * PP;
    }
    float c1[4] = {0.f,0.f,0.f,0.f};
    float c2[4] = {0.f,0.f,0.f,0.f};
    float c3[4] = {0.f,0.f,0.f,0.f};

    // ---- stage XS = x(t=0), prefetch xreg = x(t=1) ----
    float xreg[2] = {0.f, 0.f};
#pragma unroll
    for (int q = 0; q < 2; q++) {
        if (ov[q]) {
            int brow = row0 + orr[q];
            if (brow < BB) {
                sm[OFF_XS + orr[q] * XP + op[q]] = x[(size_t)brow * XW + op[q]];
                xreg[q] = x[(size_t)brow * XW + PP + op[q]];
            } else {
                sm[OFF_XS + orr[q] * XP + op[q]] = 0.f;
            }
        }
    }
    __syncthreads();

    // ================= pipelined teacher-forced loop =================
    // iteration i: L1@t=i, L2@t=i-1, L3@t=i-2, head@t=i-3
    for (int i = 0; i < TSTEPS + 3; i++) {
        const bool doL1 = (i < TSTEPS);
        const bool doL2 = (i >= 1) && (i < TSTEPS + 1);
        const bool doL3 = (i >= 2) && (i < TSTEPS + 2);
        const bool doHd = (i >= 3);
        const int  th   = i - 3;

        // ---------- Phase A: all gates + head ----------
        if (doL1) {
            uint64_t acc[NB];
#pragma unroll
            for (int r = 0; r < NB; r++) acc[r] = pack2(bg1, 0.f);
#pragma unroll
            for (int c = 0; c < XP / 4; c++) {
#pragma unroll
                for (int r = 0; r < NB; r++) {
                    ulonglong2 v = *(const ulonglong2*)(sm + OFF_XS + r * XP + c * 4);
                    ffma2(acc[r], w1x2[2 * c    ], v.x);
                    ffma2(acc[r], w1x2[2 * c + 1], v.y);
                }
            }
#pragma unroll
            for (int c = 0; c < KP / 4; c++) {
#pragma unroll
                for (int r = 0; r < NB; r++) {
                    ulonglong2 v = *(const ulonglong2*)(sm + OFF_HS1 + r * KP + c * 4);
                    ffma2(acc[r], w1h2[2 * c    ], v.x);
                    ffma2(acc[r], w1h2[2 * c + 1], v.y);
                }
            }
            if (gok) {
#pragma unroll
                for (int r = 0; r < NB; r++) sm[OFF_GS1 + r * GG + g] = hadd2(acc[r]);
            }
        }
        if (doL2)
            gates23(sm + OFF_WP2, sm + OFF_HS1, sm + OFF_HS2, sm + OFF_B2,
                    sm + OFF_GS2, pp2, pok, rbase2);
        if (doL3)
            gates23(sm + OFF_WP3, sm + OFF_HS2, sm + OFF_HS3, sm + OFF_B3,
                    sm + OFF_GS3, pp2, pok, rbase2);
        if (doHd) {
#pragma unroll
            for (int q = 0; q < 2; q++) {
                if (ov[q]) {
                    int r = orr[q], p = op[q];
                    uint64_t acc = pack2(sm[OFF_BLIN + p], 0.f);
#pragma unroll
                    for (int c = 0; c < KP / 4; c++) {
                        ulonglong2 w = *(const ulonglong2*)(sm + OFF_WLIN + p * KP + c * 4);
                        ulonglong2 h = *(const ulonglong2*)(sm + OFF_HS3  + r * KP + c * 4);
                        ffma2(acc, w.x, h.x);
                        ffma2(acc, w.y, h.y);
                    }
                    float res = hadd2(acc);
                    int brow = row0 + r;
                    if (brow < BB) out[(size_t)brow * OUTW + th * PP + p] = res;
                    if (th == TSTEPS - 1) sm[OFF_XS + r * XP + p] = res;
                }
            }
        }
        __syncthreads();                       // SA: gates/head done

        // ---------- Phase B: activations + input staging ----------
        if (doL1) act_layer(sm + OFF_GS1, sm + OFF_HS1, c1, ar, aj, av);
        if (doL2) act_layer(sm + OFF_GS2, sm + OFF_HS2, c2, ar, aj, av);
        if (doL3) act_layer(sm + OFF_GS3, sm + OFF_HS3, c3, ar, aj, av);
        if (i + 1 < TSTEPS) {
#pragma unroll
            for (int q = 0; q < 2; q++)
                if (ov[q]) sm[OFF_XS + orr[q] * XP + op[q]] = xreg[q];
            if (i + 2 < TSTEPS) {
#pragma unroll
                for (int q = 0; q < 2; q++) {
                    if (ov[q]) {
                        int brow = row0 + orr[q];
                        xreg[q] = (brow < BB)
                            ? x[(size_t)brow * XW + (i + 2) * PP + op[q]] : 0.f;
                    }
                }
            }
        }
        __syncthreads();                       // SB: H/X ready for next iter
    }

    // ================= sequential autoregressive tail =================
    for (int t = TSTEPS; t < TT; t++) {
        {   // L1 gates
            uint64_t acc[NB];
#pragma unroll
            for (int r = 0; r < NB; r++) acc[r] = pack2(bg1, 0.f);
#pragma unroll
            for (int c = 0; c < XP / 4; c++) {
#pragma unroll
                for (int r = 0; r < NB; r++) {
                    ulonglong2 v = *(const ulonglong2*)(sm + OFF_XS + r * XP + c * 4);
                    ffma2(acc[r], w1x2[2 * c    ], v.x);
                    ffma2(acc[r], w1x2[2 * c + 1], v.y);
                }
            }
#pragma unroll
            for (int c = 0; c < KP / 4; c++) {
#pragma unroll
                for (int r = 0; r < NB; r++) {
                    ulonglong2 v = *(const ulonglong2*)(sm + OFF_HS1 + r * KP + c * 4);
                    ffma2(acc[r], w1h2[2 * c    ], v.x);
                    ffma2(acc[r], w1h2[2 * c + 1], v.y);
                }
            }
            if (gok) {
#pragma unroll
                for (int r = 0; r < NB; r++) sm[OFF_GS1 + r * GG + g] = hadd2(acc[r]);
            }
        }
        __syncthreads();
        act_layer(sm + OFF_GS1, sm + OFF_HS1, c1, ar, aj, av);
        __syncthreads();
        gates23(sm + OFF_WP2, sm + OFF_HS1, sm + OFF_HS2, sm + OFF_B2,
                sm + OFF_GS2, pp2, pok, rbase2);
        __syncthreads();
        act_layer(sm + OFF_GS2, sm + OFF_HS2, c2, ar, aj, av);
        __syncthreads();
        gates23(sm + OFF_WP3, sm + OFF_HS2, sm + OFF_HS3, sm + OFF_B3,
                sm + OFF_GS3, pp2, pok, rbase2);
        __syncthreads();
        act_layer(sm + OFF_GS3, sm + OFF_HS3, c3, ar, aj, av);
        __syncthreads();
#pragma unroll
        for (int q = 0; q < 2; q++) {
            if (ov[q]) {
                int r = orr[q], p = op[q];
                uint64_t acc = pack2(sm[OFF_BLIN + p], 0.f);
#pragma unroll
                for (int c = 0; c < KP / 4; c++) {
                    ulonglong2 w = *(const ulonglong2*)(sm + OFF_WLIN + p * KP + c * 4);
                    ulonglong2 h = *(const ulonglong2*)(sm + OFF_HS3  + r * KP + c * 4);
                    ffma2(acc, w.x, h.x);
                    ffma2(acc, w.y, h.y);
                }
                float res = hadd2(acc);
                int brow = row0 + r;
                if (brow < BB) out[(size_t)brow * OUTW + t * PP + p] = res;
                sm[OFF_XS + r * XP + p] = res;
            }
        }
        __syncthreads();                       // XS ready for next t
    }
}

extern "C" void kernel_launch(void* const* d_in, const int* in_sizes, int n_in,
                              void* d_out, int out_size)
{
    const float* x    = (const float*)d_in[0];
    const float* Wih1 = (const float*)d_in[1];
    const float* Whh1 = (const float*)d_in[2];
    const float* bih1 = (const float*)d_in[3];
    const float* bhh1 = (const float*)d_in[4];
    const float* Wih2 = (const float*)d_in[5];
    const float* Whh2 = (const float*)d_in[6];
    const float* bih2 = (const float*)d_in[7];
    const float* bhh2 = (const float*)d_in[8];
    const float* Wih3 = (const float*)d_in[9];
    const float* Whh3 = (const float*)d_in[10];
    const float* bih3 = (const float*)d_in[11];
    const float* bhh3 = (const float*)d_in[12];
    const float* Wlin = (const float*)d_in[13];
    const float* blin = (const float*)d_in[14];
    float* out = (float*)d_out;

    const size_t smem = (size_t)SMEM_FLOATS * sizeof(float);
    cudaFuncSetAttribute(lstm_forward,
                         cudaFuncAttributeMaxDynamicSharedMemorySize, (int)smem);
    lstm_forward<<<NCTA, NTHREADS, smem>>>(
        x, Wih1, Whh1, bih1, bhh1, Wih2, Whh2, bih2, bhh2,
        Wih3, Whh3, bih3, bhh3, Wlin, blin, out);
}